// round 3
// baseline (speedup 1.0000x reference)
#include <cuda_runtime.h>
#include <cuda_fp16.h>
#include <cuda_bf16.h>

// ---------------------------------------------------------------------------
// MultiResImplicitFeature R3:
//   - counting sort of points by Morton code (32^3 bins) so each warp
//     processes spatially adjacent points -> gather LDGs share 128B lines
//   - grids: fp16, channel-last, 4x4x4 tiled (1KB per tile) for locality
//   - main kernel processes sorted order, stores to original row via perm
// ---------------------------------------------------------------------------

static constexpr int NCAP = 2200000;
static constexpr int NBINS = 32768;          // 32^3 Morton bins

static constexpr int RES0 = 16, RES1 = 32, RES2 = 64, RES3 = 128;
static constexpr int S0 = RES0*RES0*RES0;
static constexpr int S1 = RES1*RES1*RES1;
static constexpr int S2 = RES2*RES2*RES2;
static constexpr int S3 = RES3*RES3*RES3;
static constexpr long long OFF0 = 0;
static constexpr long long OFF1 = (long long)S0*8;
static constexpr long long OFF2 = OFF1 + (long long)S1*8;
static constexpr long long OFF3 = OFF2 + (long long)S2*8;
static constexpr long long GTOTAL = OFF3 + (long long)S3*8;

__device__ __align__(256) __half g_grids[GTOTAL];   // tiled channel-last fp16
__device__ int   g_hist[NBINS];
__device__ int   g_offs[NBINS];
__device__ int   g_key[NCAP];
__device__ int   g_perm[NCAP];
__device__ __align__(16) float g_xs[(long long)NCAP * 4];  // padded coords, sorted order

// ---------------- helpers ----------------

__device__ __forceinline__ unsigned spread5(unsigned v) {
    // 5 bits -> bits 0,3,6,9,12
    v &= 31u;
    v = (v | (v << 8)) & 0x0000100Fu;
    v = (v | (v << 4)) & 0x000010C3u;
    v = (v | (v << 2)) & 0x00001249u;
    return v;
}

// ---------------- setup kernels ----------------

__global__ void zero_hist_kernel() {
    int i = blockIdx.x * blockDim.x + threadIdx.x;
    if (i < NBINS) g_hist[i] = 0;
}

// Transpose [8, S] fp32 channel-major -> tiled channel-last fp16.
// Tiling: 4x4x4 voxel tiles, 64 voxels * 16B = 1KB per tile.
template <int R>
__global__ void transpose_tile_h_kernel(const float* __restrict__ in) {
    constexpr int S = R * R * R;
    constexpr int TB = R / 4;
    int i = blockIdx.x * blockDim.x + threadIdx.x;
    if (i >= S) return;
    int x = i & (R - 1);
    int y = (i / R) & (R - 1);
    int z = i / (R * R);
    int tile = ((z >> 2) * TB + (y >> 2)) * TB + (x >> 2);
    int addr = (tile << 6) | ((z & 3) << 4) | ((y & 3) << 2) | (x & 3);

    __half* out;
    if (R == RES0) out = g_grids + OFF0;
    else if (R == RES1) out = g_grids + OFF1;
    else if (R == RES2) out = g_grids + OFF2;
    else out = g_grids + OFF3;

    __half v[8];
#pragma unroll
    for (int c = 0; c < 8; c++) v[c] = __float2half(__ldcs(in + (long long)c * S + i));
    *reinterpret_cast<uint4*>(out + (long long)addr * 8) =
        *reinterpret_cast<const uint4*>(v);
}

// Morton key at 32^3 + histogram.
__global__ void key_hist_kernel(const float* __restrict__ x, int n) {
    int i = blockIdx.x * blockDim.x + threadIdx.x;
    if (i >= n) return;
    float px = __ldg(x + 3LL * i + 0);
    float py = __ldg(x + 3LL * i + 1);
    float pz = __ldg(x + 3LL * i + 2);
    int cx = min(31, max(0, (int)((px + 1.0f) * 16.0f)));
    int cy = min(31, max(0, (int)((py + 1.0f) * 16.0f)));
    int cz = min(31, max(0, (int)((pz + 1.0f) * 16.0f)));
    int key = (int)(spread5(cx) | (spread5(cy) << 1) | (spread5(cz) << 2));
    g_key[i] = key;
    atomicAdd(&g_hist[key], 1);
}

// Exclusive prefix over 32768 bins. One block of 1024 threads, 32 bins each.
__global__ void scan_kernel() {
    __shared__ int s[1024];
    int t = threadIdx.x;
    int base = t * 32;
    int loc[32];
    int sum = 0;
#pragma unroll
    for (int k = 0; k < 32; k++) { loc[k] = sum; sum += g_hist[base + k]; }
    s[t] = sum;
    __syncthreads();
    // Hillis-Steele inclusive scan
    for (int off = 1; off < 1024; off <<= 1) {
        int v = (t >= off) ? s[t - off] : 0;
        __syncthreads();
        s[t] += v;
        __syncthreads();
    }
    int ex = s[t] - sum;  // exclusive prefix of this thread's chunk
#pragma unroll
    for (int k = 0; k < 32; k++) g_offs[base + k] = ex + loc[k];
}

__global__ void scatter_kernel(const float* __restrict__ x, int n) {
    int i = blockIdx.x * blockDim.x + threadIdx.x;
    if (i >= n) return;
    int key = g_key[i];
    int pos = atomicAdd(&g_offs[key], 1);
    g_perm[pos] = i;
    float px = __ldg(x + 3LL * i + 0);
    float py = __ldg(x + 3LL * i + 1);
    float pz = __ldg(x + 3LL * i + 2);
    *reinterpret_cast<float4*>(g_xs + 4LL * pos) = make_float4(px, py, pz, 0.0f);
}

// ---------------- main kernel ----------------

template <int R>
__device__ __forceinline__ void trilerp8t(const __half* __restrict__ g,
                                          float px, float py, float pz,
                                          float* __restrict__ acc) {
    constexpr int TB = R / 4;
    const float scale = 0.5f * (float)(R - 1);
    float cx = (px + 1.0f) * scale;
    float cy = (py + 1.0f) * scale;
    float cz = (pz + 1.0f) * scale;
    float fx = floorf(cx), fy = floorf(cy), fz = floorf(cz);
    int x0 = (int)fx; x0 = max(0, min(x0, R - 1));
    int y0 = (int)fy; y0 = max(0, min(y0, R - 1));
    int z0 = (int)fz; z0 = max(0, min(z0, R - 1));
    int x1 = min(x0 + 1, R - 1);
    int y1 = min(y0 + 1, R - 1);
    int z1 = min(z0 + 1, R - 1);
    float wx = cx - fx, wy = cy - fy, wz = cz - fz;

    float wxs[2] = {1.0f - wx, wx};
    float wys[2] = {1.0f - wy, wy};
    float wzs[2] = {1.0f - wz, wz};
    int bxs[2] = {x0 >> 2, x1 >> 2};
    int lxs[2] = {x0 & 3, x1 & 3};
    int bys[2] = {y0 >> 2, y1 >> 2};
    int lys[2] = {y0 & 3, y1 & 3};
    int bzs[2] = {z0 >> 2, z1 >> 2};
    int lzs[2] = {z0 & 3, z1 & 3};

#pragma unroll
    for (int dz = 0; dz < 2; dz++) {
#pragma unroll
        for (int dy = 0; dy < 2; dy++) {
            int tzy = (bzs[dz] * TB + bys[dy]) * TB;
            int lzy = (lzs[dz] << 4) | (lys[dy] << 2);
#pragma unroll
            for (int dx = 0; dx < 2; dx++) {
                int vox = (((tzy + bxs[dx]) << 6) | lzy | lxs[dx]);
                uint4 v = __ldg(reinterpret_cast<const uint4*>(g + ((long long)vox << 3)));
                float w = wzs[dz] * wys[dy] * wxs[dx];
                float2 f0 = __half22float2(*reinterpret_cast<__half2*>(&v.x));
                float2 f1 = __half22float2(*reinterpret_cast<__half2*>(&v.y));
                float2 f2 = __half22float2(*reinterpret_cast<__half2*>(&v.z));
                float2 f3 = __half22float2(*reinterpret_cast<__half2*>(&v.w));
                acc[0] = fmaf(w, f0.x, acc[0]);
                acc[1] = fmaf(w, f0.y, acc[1]);
                acc[2] = fmaf(w, f1.x, acc[2]);
                acc[3] = fmaf(w, f1.y, acc[3]);
                acc[4] = fmaf(w, f2.x, acc[4]);
                acc[5] = fmaf(w, f2.y, acc[5]);
                acc[6] = fmaf(w, f3.x, acc[6]);
                acc[7] = fmaf(w, f3.y, acc[7]);
            }
        }
    }
}

__global__ void __launch_bounds__(256)
mrif_main_kernel(float* __restrict__ out, int n) {
    int pos = blockIdx.x * blockDim.x + threadIdx.x;
    if (pos >= n) return;

    float4 p4 = *reinterpret_cast<const float4*>(g_xs + 4LL * pos);
    float px = p4.x, py = p4.y, pz = p4.z;
    int j = g_perm[pos];

    float* orow = out + (long long)j * 56;

    // ---- Fourier features ----
    {
        const float HPI = 1.57079632679489662f;
        float sc[24];
        float p[3] = {px, py, pz};
#pragma unroll
        for (int l = 0; l < 4; l++) {
#pragma unroll
            for (int d = 0; d < 3; d++) {
                float s, c;
                __sincosf(HPI * (float)(l + 1) * p[d], &s, &c);
                sc[l * 3 + d] = s;
                sc[12 + l * 3 + d] = c;
            }
        }
#pragma unroll
        for (int k = 0; k < 6; k++) {
            __stcs(reinterpret_cast<float4*>(orow) + k,
                   make_float4(sc[4*k], sc[4*k+1], sc[4*k+2], sc[4*k+3]));
        }
    }

    // ---- 4 multires trilerps ----
    float f[8];

#pragma unroll
    for (int c = 0; c < 8; c++) f[c] = 0.0f;
    trilerp8t<RES0>(g_grids + OFF0, px, py, pz, f);
    __stcs(reinterpret_cast<float4*>(orow + 24),     make_float4(f[0], f[1], f[2], f[3]));
    __stcs(reinterpret_cast<float4*>(orow + 24) + 1, make_float4(f[4], f[5], f[6], f[7]));

#pragma unroll
    for (int c = 0; c < 8; c++) f[c] = 0.0f;
    trilerp8t<RES1>(g_grids + OFF1, px, py, pz, f);
    __stcs(reinterpret_cast<float4*>(orow + 32),     make_float4(f[0], f[1], f[2], f[3]));
    __stcs(reinterpret_cast<float4*>(orow + 32) + 1, make_float4(f[4], f[5], f[6], f[7]));

#pragma unroll
    for (int c = 0; c < 8; c++) f[c] = 0.0f;
    trilerp8t<RES2>(g_grids + OFF2, px, py, pz, f);
    __stcs(reinterpret_cast<float4*>(orow + 40),     make_float4(f[0], f[1], f[2], f[3]));
    __stcs(reinterpret_cast<float4*>(orow + 40) + 1, make_float4(f[4], f[5], f[6], f[7]));

#pragma unroll
    for (int c = 0; c < 8; c++) f[c] = 0.0f;
    trilerp8t<RES3>(g_grids + OFF3, px, py, pz, f);
    __stcs(reinterpret_cast<float4*>(orow + 48),     make_float4(f[0], f[1], f[2], f[3]));
    __stcs(reinterpret_cast<float4*>(orow + 48) + 1, make_float4(f[4], f[5], f[6], f[7]));
}

// ---------------- launch ----------------

extern "C" void kernel_launch(void* const* d_in, const int* in_sizes, int n_in,
                              void* d_out, int out_size) {
    const float* x  = (const float*)d_in[0];
    const float* g0 = (const float*)d_in[1];
    const float* g1 = (const float*)d_in[2];
    const float* g2 = (const float*)d_in[3];
    const float* g3 = (const float*)d_in[4];
    float* out = (float*)d_out;

    int n = in_sizes[0] / 3;
    if (n > NCAP) n = NCAP;

    const int TT = 256;
    zero_hist_kernel<<<(NBINS + TT - 1) / TT, TT>>>();
    transpose_tile_h_kernel<RES0><<<(S0 + TT - 1) / TT, TT>>>(g0);
    transpose_tile_h_kernel<RES1><<<(S1 + TT - 1) / TT, TT>>>(g1);
    transpose_tile_h_kernel<RES2><<<(S2 + TT - 1) / TT, TT>>>(g2);
    transpose_tile_h_kernel<RES3><<<(S3 + TT - 1) / TT, TT>>>(g3);
    key_hist_kernel<<<(n + TT - 1) / TT, TT>>>(x, n);
    scan_kernel<<<1, 1024>>>();
    scatter_kernel<<<(n + TT - 1) / TT, TT>>>(x, n);
    mrif_main_kernel<<<(n + 255) / 256, 256>>>(out, n);
}

// round 4
// speedup vs baseline: 1.4520x; 1.4520x over previous
#include <cuda_runtime.h>
#include <cuda_fp16.h>
#include <cuda_bf16.h>

// ---------------------------------------------------------------------------
// MultiResImplicitFeature R4: two-pass.
//  Pass A (sorted by 32^3 Morton bin): gather trilerp features from tiled
//    fp16 channel-last grids (warp-local spatial locality -> few L1tex
//    wavefronts), stage contiguously as fp16 (64 B/point).
//  Pass B (original order): coalesced x read, sin/cos, random 64-B staged
//    read via inverse permutation, assemble rows in smem, flush the block's
//    output region with fully coalesced stores.
// ---------------------------------------------------------------------------

static constexpr int NCAP = 2200000;
static constexpr int NBINS = 32768;          // 32^3 Morton bins

static constexpr int RES0 = 16, RES1 = 32, RES2 = 64, RES3 = 128;
static constexpr int S0 = RES0*RES0*RES0;
static constexpr int S1 = RES1*RES1*RES1;
static constexpr int S2 = RES2*RES2*RES2;
static constexpr int S3 = RES3*RES3*RES3;
static constexpr long long OFF0 = 0;
static constexpr long long OFF1 = (long long)S0*8;
static constexpr long long OFF2 = OFF1 + (long long)S1*8;
static constexpr long long OFF3 = OFF2 + (long long)S2*8;
static constexpr long long GTOTAL = OFF3 + (long long)S3*8;

__device__ __align__(256) __half g_grids[GTOTAL];          // tiled channel-last fp16
__device__ int   g_hist[NBINS];
__device__ int   g_offs[NBINS];
__device__ int   g_inv[NCAP];                              // original idx -> sorted pos
__device__ __align__(16) float  g_xs[(long long)NCAP * 4]; // coords in sorted order
__device__ __align__(16) __half g_feat[(long long)NCAP * 32]; // staged grid feats

// ---------------- helpers ----------------

__device__ __forceinline__ unsigned spread5(unsigned v) {
    v &= 31u;
    v = (v | (v << 8)) & 0x0000100Fu;
    v = (v | (v << 4)) & 0x000010C3u;
    v = (v | (v << 2)) & 0x00001249u;
    return v;
}

__device__ __forceinline__ int morton_key(float px, float py, float pz) {
    int cx = min(31, max(0, (int)((px + 1.0f) * 16.0f)));
    int cy = min(31, max(0, (int)((py + 1.0f) * 16.0f)));
    int cz = min(31, max(0, (int)((pz + 1.0f) * 16.0f)));
    return (int)(spread5(cx) | (spread5(cy) << 1) | (spread5(cz) << 2));
}

// ---------------- setup kernels ----------------

__global__ void zero_hist_kernel() {
    int i = blockIdx.x * blockDim.x + threadIdx.x;
    if (i < NBINS) g_hist[i] = 0;
}

// [8,S] fp32 channel-major -> tiled (4x4x4) channel-last fp16.
template <int R>
__global__ void transpose_tile_h_kernel(const float* __restrict__ in) {
    constexpr int S = R * R * R;
    constexpr int TB = R / 4;
    int i = blockIdx.x * blockDim.x + threadIdx.x;
    if (i >= S) return;
    int x = i & (R - 1);
    int y = (i / R) & (R - 1);
    int z = i / (R * R);
    int tile = ((z >> 2) * TB + (y >> 2)) * TB + (x >> 2);
    int addr = (tile << 6) | ((z & 3) << 4) | ((y & 3) << 2) | (x & 3);

    __half* out;
    if (R == RES0) out = g_grids + OFF0;
    else if (R == RES1) out = g_grids + OFF1;
    else if (R == RES2) out = g_grids + OFF2;
    else out = g_grids + OFF3;

    __half v[8];
#pragma unroll
    for (int c = 0; c < 8; c++) v[c] = __float2half(__ldcs(in + (long long)c * S + i));
    *reinterpret_cast<uint4*>(out + (long long)addr * 8) =
        *reinterpret_cast<const uint4*>(v);
}

__global__ void key_hist_kernel(const float* __restrict__ x, int n) {
    int i = blockIdx.x * blockDim.x + threadIdx.x;
    if (i >= n) return;
    float px = __ldg(x + 3LL * i + 0);
    float py = __ldg(x + 3LL * i + 1);
    float pz = __ldg(x + 3LL * i + 2);
    atomicAdd(&g_hist[morton_key(px, py, pz)], 1);
}

// Exclusive prefix over 32768 bins. One block, 1024 threads x 32 bins.
__global__ void scan_kernel() {
    __shared__ int s[1024];
    int t = threadIdx.x;
    int base = t * 32;
    int loc[32];
    int sum = 0;
#pragma unroll
    for (int k = 0; k < 32; k++) { loc[k] = sum; sum += g_hist[base + k]; }
    s[t] = sum;
    __syncthreads();
    for (int off = 1; off < 1024; off <<= 1) {
        int v = (t >= off) ? s[t - off] : 0;
        __syncthreads();
        s[t] += v;
        __syncthreads();
    }
    int ex = s[t] - sum;
#pragma unroll
    for (int k = 0; k < 32; k++) g_offs[base + k] = ex + loc[k];
}

__global__ void scatter_kernel(const float* __restrict__ x, int n) {
    int i = blockIdx.x * blockDim.x + threadIdx.x;
    if (i >= n) return;
    float px = __ldg(x + 3LL * i + 0);
    float py = __ldg(x + 3LL * i + 1);
    float pz = __ldg(x + 3LL * i + 2);
    int pos = atomicAdd(&g_offs[morton_key(px, py, pz)], 1);
    g_inv[i] = pos;
    *reinterpret_cast<float4*>(g_xs + 4LL * pos) = make_float4(px, py, pz, 0.0f);
}

// ---------------- pass A: sorted gather ----------------

template <int R>
__device__ __forceinline__ void trilerp8t(const __half* __restrict__ g,
                                          float px, float py, float pz,
                                          float* __restrict__ acc) {
    constexpr int TB = R / 4;
    const float scale = 0.5f * (float)(R - 1);
    float cx = (px + 1.0f) * scale;
    float cy = (py + 1.0f) * scale;
    float cz = (pz + 1.0f) * scale;
    float fx = floorf(cx), fy = floorf(cy), fz = floorf(cz);
    int x0 = (int)fx; x0 = max(0, min(x0, R - 1));
    int y0 = (int)fy; y0 = max(0, min(y0, R - 1));
    int z0 = (int)fz; z0 = max(0, min(z0, R - 1));
    int x1 = min(x0 + 1, R - 1);
    int y1 = min(y0 + 1, R - 1);
    int z1 = min(z0 + 1, R - 1);
    float wx = cx - fx, wy = cy - fy, wz = cz - fz;

    float wxs[2] = {1.0f - wx, wx};
    float wys[2] = {1.0f - wy, wy};
    float wzs[2] = {1.0f - wz, wz};
    int bxs[2] = {x0 >> 2, x1 >> 2};
    int lxs[2] = {x0 & 3, x1 & 3};
    int bys[2] = {y0 >> 2, y1 >> 2};
    int lys[2] = {y0 & 3, y1 & 3};
    int bzs[2] = {z0 >> 2, z1 >> 2};
    int lzs[2] = {z0 & 3, z1 & 3};

#pragma unroll
    for (int dz = 0; dz < 2; dz++) {
#pragma unroll
        for (int dy = 0; dy < 2; dy++) {
            int tzy = (bzs[dz] * TB + bys[dy]) * TB;
            int lzy = (lzs[dz] << 4) | (lys[dy] << 2);
#pragma unroll
            for (int dx = 0; dx < 2; dx++) {
                int vox = (((tzy + bxs[dx]) << 6) | lzy | lxs[dx]);
                uint4 v = __ldg(reinterpret_cast<const uint4*>(g + ((long long)vox << 3)));
                float w = wzs[dz] * wys[dy] * wxs[dx];
                float2 f0 = __half22float2(*reinterpret_cast<__half2*>(&v.x));
                float2 f1 = __half22float2(*reinterpret_cast<__half2*>(&v.y));
                float2 f2 = __half22float2(*reinterpret_cast<__half2*>(&v.z));
                float2 f3 = __half22float2(*reinterpret_cast<__half2*>(&v.w));
                acc[0] = fmaf(w, f0.x, acc[0]);
                acc[1] = fmaf(w, f0.y, acc[1]);
                acc[2] = fmaf(w, f1.x, acc[2]);
                acc[3] = fmaf(w, f1.y, acc[3]);
                acc[4] = fmaf(w, f2.x, acc[4]);
                acc[5] = fmaf(w, f2.y, acc[5]);
                acc[6] = fmaf(w, f3.x, acc[6]);
                acc[7] = fmaf(w, f3.y, acc[7]);
            }
        }
    }
}

__global__ void __launch_bounds__(256)
mrif_gather_kernel(int n) {
    int pos = blockIdx.x * blockDim.x + threadIdx.x;
    if (pos >= n) return;

    float4 p4 = *reinterpret_cast<const float4*>(g_xs + 4LL * pos);
    float px = p4.x, py = p4.y, pz = p4.z;

    float f[32];
#pragma unroll
    for (int c = 0; c < 32; c++) f[c] = 0.0f;
    trilerp8t<RES0>(g_grids + OFF0, px, py, pz, f + 0);
    trilerp8t<RES1>(g_grids + OFF1, px, py, pz, f + 8);
    trilerp8t<RES2>(g_grids + OFF2, px, py, pz, f + 16);
    trilerp8t<RES3>(g_grids + OFF3, px, py, pz, f + 24);

    __half h[32];
#pragma unroll
    for (int c = 0; c < 32; c++) h[c] = __float2half(f[c]);
    uint4* dst = reinterpret_cast<uint4*>(g_feat + 32LL * pos);
    const uint4* src = reinterpret_cast<const uint4*>(h);
#pragma unroll
    for (int k = 0; k < 4; k++) __stcs((float4*)(dst + k), *(const float4*)(src + k));
}

// ---------------- pass B: original-order assembly + coalesced flush -------

static constexpr int WB = 128;     // rows per block
static constexpr int RSTRIDE = 57; // padded row stride in floats (gcd(57,32)=1)

__global__ void __launch_bounds__(WB)
mrif_write_kernel(const float* __restrict__ x, float* __restrict__ out, int n) {
    __shared__ float s[WB * RSTRIDE];   // 29184 B
    int base = blockIdx.x * WB;
    int t = threadIdx.x;
    int i = base + t;
    int valid = min(WB, n - base);

    if (t < valid) {
        float px = __ldg(x + 3LL * i + 0);
        float py = __ldg(x + 3LL * i + 1);
        float pz = __ldg(x + 3LL * i + 2);

        const float HPI = 1.57079632679489662f;
        float p[3] = {px, py, pz};
        float* row = s + t * RSTRIDE;
#pragma unroll
        for (int l = 0; l < 4; l++) {
#pragma unroll
            for (int d = 0; d < 3; d++) {
                float sv, cv;
                __sincosf(HPI * (float)(l + 1) * p[d], &sv, &cv);
                row[l * 3 + d] = sv;
                row[12 + l * 3 + d] = cv;
            }
        }

        int pos = g_inv[i];
        const uint4* src = reinterpret_cast<const uint4*>(g_feat + 32LL * pos);
#pragma unroll
        for (int k = 0; k < 4; k++) {
            uint4 v = __ldcs(src + k);
            __half2 h0 = *reinterpret_cast<__half2*>(&v.x);
            __half2 h1 = *reinterpret_cast<__half2*>(&v.y);
            __half2 h2 = *reinterpret_cast<__half2*>(&v.z);
            __half2 h3 = *reinterpret_cast<__half2*>(&v.w);
            float2 f0 = __half22float2(h0);
            float2 f1 = __half22float2(h1);
            float2 f2 = __half22float2(h2);
            float2 f3 = __half22float2(h3);
            float* d = row + 24 + k * 8;
            d[0] = f0.x; d[1] = f0.y; d[2] = f1.x; d[3] = f1.y;
            d[4] = f2.x; d[5] = f2.y; d[6] = f3.x; d[7] = f3.y;
        }
    }
    __syncthreads();

    // Coalesced flush of valid*56 contiguous floats.
    int total = valid * 56;
    float* obase = out + (long long)base * 56;
    for (int w = t * 4; w < total; w += WB * 4) {
        int r = w / 56;          // 4-word group never crosses a row (56 % 4 == 0)
        int c = w - r * 56;
        const float* sp = s + r * RSTRIDE + c;
        __stcs(reinterpret_cast<float4*>(obase + w),
               make_float4(sp[0], sp[1], sp[2], sp[3]));
    }
}

// ---------------- launch ----------------

extern "C" void kernel_launch(void* const* d_in, const int* in_sizes, int n_in,
                              void* d_out, int out_size) {
    const float* x  = (const float*)d_in[0];
    const float* g0 = (const float*)d_in[1];
    const float* g1 = (const float*)d_in[2];
    const float* g2 = (const float*)d_in[3];
    const float* g3 = (const float*)d_in[4];
    float* out = (float*)d_out;

    int n = in_sizes[0] / 3;
    if (n > NCAP) n = NCAP;

    const int TT = 256;
    zero_hist_kernel<<<(NBINS + TT - 1) / TT, TT>>>();
    transpose_tile_h_kernel<RES0><<<(S0 + TT - 1) / TT, TT>>>(g0);
    transpose_tile_h_kernel<RES1><<<(S1 + TT - 1) / TT, TT>>>(g1);
    transpose_tile_h_kernel<RES2><<<(S2 + TT - 1) / TT, TT>>>(g2);
    transpose_tile_h_kernel<RES3><<<(S3 + TT - 1) / TT, TT>>>(g3);
    key_hist_kernel<<<(n + TT - 1) / TT, TT>>>(x, n);
    scan_kernel<<<1, 1024>>>();
    scatter_kernel<<<(n + TT - 1) / TT, TT>>>(x, n);
    mrif_gather_kernel<<<(n + 255) / 256, 256>>>(n);
    mrif_write_kernel<<<(n + WB - 1) / WB, WB>>>(x, out, n);
}